// round 1
// baseline (speedup 1.0000x reference)
#include <cuda_runtime.h>
#include <cstdint>

#define NN   55296      // 6*96*96 nodes
#define NE   221184     // edges
#define H    32
#define HH   1024       // H*H
#define BB   2          // batch

// -------- device scratch (static: allocation-free kernel_launch) --------
__device__ float g_We[(size_t)NE * HH];        // 906 MB  [E][h*32+o]
__device__ float g_node[(size_t)BB * NN * H];  // current node feats
__device__ float g_hidden[(size_t)BB * NN * H];
__device__ float g_agg[(size_t)BB * NN * H];

#define FULL 0xffffffffu

// ---------------------------------------------------------------
// h0 = relu(x@pw1 + pb1)@pw2 + pb2   (warp per (b,node), lane = channel)
// ---------------------------------------------------------------
__global__ __launch_bounds__(256) void k_h0(
    const float* __restrict__ x,
    const float* __restrict__ pw1, const float* __restrict__ pb1,
    const float* __restrict__ pw2, const float* __restrict__ pb2)
{
    int warp = (blockIdx.x * blockDim.x + threadIdx.x) >> 5;
    int lane = threadIdx.x & 31;
    if (warp >= BB * NN) return;
    size_t base = (size_t)warp * H;

    float v = x[base + lane];
    float acc = pb1[lane];
#pragma unroll
    for (int c = 0; c < H; c++)
        acc = fmaf(__shfl_sync(FULL, v, c), pw1[c * H + lane], acc);
    float hid = fmaxf(acc, 0.f);

    float acc2 = pb2[lane];
#pragma unroll
    for (int k = 0; k < H; k++)
        acc2 = fmaf(__shfl_sync(FULL, hid, k), pw2[k * H + lane], acc2);

    g_node[base + lane]   = acc2;
    g_hidden[base + lane] = acc2;
}

// ---------------------------------------------------------------
// We[e] = relu(rel[e]@ew1 + eb1) @ ew2 + eb2      (warp per edge)
// lane l owns j = 4*l + 128*c (c=0..7) as float4 accumulators.
// relu zeros (~50%) skipped via warp-uniform ballot loop.
// ---------------------------------------------------------------
__global__ __launch_bounds__(256) void k_We(
    const float* __restrict__ rel,
    const float* __restrict__ ew1, const float* __restrict__ eb1,
    const float* __restrict__ ew2, const float* __restrict__ eb2)
{
    int e    = (blockIdx.x * blockDim.x + threadIdx.x) >> 5;
    int lane = threadIdx.x & 31;
    if (e >= NE) return;

    // hid[lane]
    const float* r = rel + (size_t)e * 4;
    float acc = eb1[lane];
#pragma unroll
    for (int c = 0; c < 4; c++)
        acc = fmaf(r[c], ew1[c * H + lane], acc);
    float hid = fmaxf(acc, 0.f);

    float4 o0, o1, o2, o3, o4, o5, o6, o7;
    {
        const float4* b = (const float4*)eb2;   // 256 float4
        o0 = b[lane];        o1 = b[lane + 32];  o2 = b[lane + 64];  o3 = b[lane + 96];
        o4 = b[lane + 128];  o5 = b[lane + 160]; o6 = b[lane + 192]; o7 = b[lane + 224];
    }

    unsigned mask = __ballot_sync(FULL, hid > 0.f);
    while (mask) {
        int k = __ffs(mask) - 1;
        mask &= mask - 1;
        float hk = __shfl_sync(FULL, hid, k);
        const float4* w = (const float4*)(ew2 + (size_t)k * HH);
#define ACC(oc, idx) { float4 wv = w[idx]; \
        oc.x = fmaf(hk, wv.x, oc.x); oc.y = fmaf(hk, wv.y, oc.y); \
        oc.z = fmaf(hk, wv.z, oc.z); oc.w = fmaf(hk, wv.w, oc.w); }
        ACC(o0, lane)       ACC(o1, lane + 32)  ACC(o2, lane + 64)  ACC(o3, lane + 96)
        ACC(o4, lane + 128) ACC(o5, lane + 160) ACC(o6, lane + 192) ACC(o7, lane + 224)
#undef ACC
    }

    float4* dst = (float4*)(g_We + (size_t)e * HH);
    dst[lane]       = o0; dst[lane + 32]  = o1; dst[lane + 64]  = o2; dst[lane + 96]  = o3;
    dst[lane + 128] = o4; dst[lane + 160] = o5; dst[lane + 192] = o6; dst[lane + 224] = o7;
}

// ---------------------------------------------------------------
// zero agg
// ---------------------------------------------------------------
__global__ __launch_bounds__(256) void k_zero()
{
    size_t i = (size_t)blockIdx.x * blockDim.x + threadIdx.x;
    if (i < (size_t)BB * NN * H) g_agg[i] = 0.f;
}

// ---------------------------------------------------------------
// message + scatter:  agg[b,dst] += node[b,src] @ We[e]   (warp per edge)
// ---------------------------------------------------------------
__global__ __launch_bounds__(256) void k_msg(
    const int* __restrict__ esrc, const int* __restrict__ edst)
{
    int e    = (blockIdx.x * blockDim.x + threadIdx.x) >> 5;
    int lane = threadIdx.x & 31;
    if (e >= NE) return;

    int s = esrc[e];
    int d = edst[e];

    float n0 = g_node[(size_t)s * H + lane];
    float n1 = g_node[(size_t)(NN + s) * H + lane];

    const float* w = g_We + (size_t)e * HH;
    float a0 = 0.f, a1 = 0.f;
#pragma unroll
    for (int h = 0; h < H; h++) {
        float we = __ldcs(w + h * H + lane);   // streaming: no reuse within a step
        a0 = fmaf(__shfl_sync(FULL, n0, h), we, a0);
        a1 = fmaf(__shfl_sync(FULL, n1, h), we, a1);
    }
    atomicAdd(g_agg + (size_t)d * H + lane, a0);
    atomicAdd(g_agg + (size_t)(NN + d) * H + lane, a1);
}

// ---------------------------------------------------------------
// node = relu(agg + conv_b); GRU update. Thread per (b,node).
// Weights read as warp-uniform float4 (broadcast wavefronts).
// ---------------------------------------------------------------
__global__ __launch_bounds__(256) void k_gru(
    const float* __restrict__ conv_b,
    const float* __restrict__ wih, const float* __restrict__ whh,
    const float* __restrict__ bih, const float* __restrict__ bhh,
    float* __restrict__ out, int write_out)
{
    int n = blockIdx.x * blockDim.x + threadIdx.x;
    if (n >= BB * NN) return;
    size_t base = (size_t)n * H;

    float nd[H], hd[H];
    {
        const float4* av = (const float4*)(g_agg + base);
        const float4* hv = (const float4*)(g_hidden + base);
        const float4* cv = (const float4*)conv_b;
#pragma unroll
        for (int q = 0; q < 8; q++) {
            float4 a = av[q], c = cv[q], h4 = hv[q];
            nd[4*q+0] = fmaxf(a.x + c.x, 0.f);
            nd[4*q+1] = fmaxf(a.y + c.y, 0.f);
            nd[4*q+2] = fmaxf(a.z + c.z, 0.f);
            nd[4*q+3] = fmaxf(a.w + c.w, 0.f);
            hd[4*q+0] = h4.x; hd[4*q+1] = h4.y; hd[4*q+2] = h4.z; hd[4*q+3] = h4.w;
        }
    }

    const float4* wi = (const float4*)wih;   // [96][8] float4, row j at wi[j*8..]
    const float4* wh = (const float4*)whh;

#pragma unroll 1
    for (int o = 0; o < H; o++) {
        float xr = 0.f, xz = 0.f, xn = 0.f, hr = 0.f, hz = 0.f, hn = 0.f;
#pragma unroll
        for (int q = 0; q < 8; q++) {
            float4 w;
#define DOT(accv, srcarr, row) { w = (row)[q]; \
            accv = fmaf(srcarr[4*q+0], w.x, accv); accv = fmaf(srcarr[4*q+1], w.y, accv); \
            accv = fmaf(srcarr[4*q+2], w.z, accv); accv = fmaf(srcarr[4*q+3], w.w, accv); }
            DOT(xr, nd, wi + (size_t)(o)      * 8)
            DOT(xz, nd, wi + (size_t)(o + 32) * 8)
            DOT(xn, nd, wi + (size_t)(o + 64) * 8)
            DOT(hr, hd, wh + (size_t)(o)      * 8)
            DOT(hz, hd, wh + (size_t)(o + 32) * 8)
            DOT(hn, hd, wh + (size_t)(o + 64) * 8)
#undef DOT
        }
        float rg = 1.f / (1.f + expf(-(xr + hr + bih[o]      + bhh[o])));
        float zg = 1.f / (1.f + expf(-(xz + hz + bih[o + 32] + bhh[o + 32])));
        float ng = tanhf(xn + bih[o + 64] + rg * (hn + bhh[o + 64]));
        float hprev = g_hidden[base + o];          // L1 hit (line already touched)
        float newh = (1.f - zg) * ng + zg * hprev;
        g_hidden[base + o] = newh;
        g_node[base + o]   = newh;
        if (write_out) out[base + o] = newh;
    }
}

// ---------------------------------------------------------------
extern "C" void kernel_launch(void* const* d_in, const int* in_sizes, int n_in,
                              void* d_out, int out_size)
{
    const float* x      = (const float*)d_in[0];
    const float* rel    = (const float*)d_in[1];
    const float* pw1    = (const float*)d_in[2];
    const float* pb1    = (const float*)d_in[3];
    const float* pw2    = (const float*)d_in[4];
    const float* pb2    = (const float*)d_in[5];
    const float* ew1    = (const float*)d_in[6];
    const float* eb1    = (const float*)d_in[7];
    const float* ew2    = (const float*)d_in[8];
    const float* eb2    = (const float*)d_in[9];
    const float* conv_b = (const float*)d_in[10];
    const float* wih    = (const float*)d_in[11];
    const float* whh    = (const float*)d_in[12];
    const float* bih    = (const float*)d_in[13];
    const float* bhh    = (const float*)d_in[14];
    const int*   esrc   = (const int*)d_in[15];
    const int*   edst   = (const int*)d_in[16];
    float* out = (float*)d_out;

    // 110592 warps for h0 -> 13824 blocks of 256 (8 warps each)
    k_h0<<<13824, 256>>>(x, pw1, pb1, pw2, pb2);
    // 221184 warps for We/msg -> 27648 blocks
    k_We<<<27648, 256>>>(rel, ew1, eb1, ew2, eb2);

    for (int s = 0; s < 3; s++) {
        k_zero<<<13824, 256>>>();                       // 3,538,944 elements exactly
        k_msg<<<27648, 256>>>(esrc, edst);
        k_gru<<<432, 256>>>(conv_b, wih, whh, bih, bhh, out, (s == 2) ? 1 : 0);
    }
}

// round 5
// speedup vs baseline: 1.3462x; 1.3462x over previous
#include <cuda_runtime.h>
#include <cuda_fp16.h>
#include <cstdint>

#define NN   55296      // 6*96*96 nodes
#define NE   221184     // edges
#define H    32
#define HH   1024       // H*H
#define BB   2          // batch

// -------- device scratch (static: allocation-free kernel_launch) --------
__device__ __half g_We[(size_t)NE * HH];       // 453 MB  [E][h*32+o] fp16
__device__ float g_node[(size_t)BB * NN * H];
__device__ float g_hidden[(size_t)BB * NN * H];
__device__ float g_agg[(size_t)BB * NN * H];

#define FULL 0xffffffffu
typedef unsigned long long ull;

// ---- packed f32x2 helpers (Blackwell fma.rn.f32x2) ----
__device__ __forceinline__ ull pack2(float x) {
    ull r; asm("mov.b64 %0, {%1, %2};" : "=l"(r) : "f"(x), "f"(x)); return r;
}
__device__ __forceinline__ void fma2(ull& d, ull a, ull b) {
    asm("fma.rn.f32x2 %0, %1, %2, %0;" : "+l"(d) : "l"(a), "l"(b));
}
__device__ __forceinline__ float2 unpack2(ull v) {
    float2 f; asm("mov.b64 {%0, %1}, %2;" : "=f"(f.x), "=f"(f.y) : "l"(v)); return f;
}

// fast activations (MUFU-based, ~1e-6 err, overflow-safe)
__device__ __forceinline__ float fsigmoid(float x) {
    return __fdividef(1.f, 1.f + __expf(-x));
}
__device__ __forceinline__ float ftanh(float x) {
    return 1.f - __fdividef(2.f, __expf(2.f * x) + 1.f);
}

// ---------------------------------------------------------------
// h0 = relu(x@pw1 + pb1)@pw2 + pb2   (warp per (b,node), lane = channel)
// ---------------------------------------------------------------
__global__ __launch_bounds__(256) void k_h0(
    const float* __restrict__ x,
    const float* __restrict__ pw1, const float* __restrict__ pb1,
    const float* __restrict__ pw2, const float* __restrict__ pb2)
{
    int warp = (blockIdx.x * blockDim.x + threadIdx.x) >> 5;
    int lane = threadIdx.x & 31;
    if (warp >= BB * NN) return;
    size_t base = (size_t)warp * H;

    float v = x[base + lane];
    float acc = pb1[lane];
#pragma unroll
    for (int c = 0; c < H; c++)
        acc = fmaf(__shfl_sync(FULL, v, c), pw1[c * H + lane], acc);
    float hid = fmaxf(acc, 0.f);

    float acc2 = pb2[lane];
#pragma unroll
    for (int k = 0; k < H; k++)
        acc2 = fmaf(__shfl_sync(FULL, hid, k), pw2[k * H + lane], acc2);

    g_node[base + lane]   = acc2;
    g_hidden[base + lane] = acc2;
}

// ---------------------------------------------------------------
// We[e] = relu(rel[e]@ew1 + eb1) @ ew2 + eb2   -> fp16
// 4 edges per warp: ew2 row loads shared in registers across the 4 edges,
// union-ballot sparsity over k, packed f32x2 FMA.
// lane owns float indices 4*(lane+32*jj)..+3 of each edge's 1024-vector.
// ---------------------------------------------------------------
__global__ __launch_bounds__(128, 2) void k_We(
    const float* __restrict__ rel,
    const float* __restrict__ ew1, const float* __restrict__ eb1,
    const float* __restrict__ ew2, const float* __restrict__ eb2)
{
    int warp = (blockIdx.x * blockDim.x + threadIdx.x) >> 5;
    int lane = threadIdx.x & 31;
    if (warp >= NE / 4) return;
    int e4 = warp * 4;

    // hid for 4 edges (lane = hidden channel)
    float h0v, h1v, h2v, h3v;
    {
        float b = eb1[lane];
        float w0 = ew1[0 * H + lane], w1 = ew1[1 * H + lane],
              w2 = ew1[2 * H + lane], w3 = ew1[3 * H + lane];
#define HID(dst, e) { const float* r = rel + (size_t)(e4 + e) * 4; \
        float a = b; a = fmaf(r[0], w0, a); a = fmaf(r[1], w1, a); \
        a = fmaf(r[2], w2, a); a = fmaf(r[3], w3, a); dst = fmaxf(a, 0.f); }
        HID(h0v, 0) HID(h1v, 1) HID(h2v, 2) HID(h3v, 3)
#undef HID
    }

    // accumulators: 4 edges x 16 f32x2 (init from eb2)
    ull acc[4][16];
    {
        const ulonglong2* b2 = (const ulonglong2*)eb2;
#pragma unroll
        for (int jj = 0; jj < 8; jj++) {
            ulonglong2 bv = b2[lane + 32 * jj];
#pragma unroll
            for (int e = 0; e < 4; e++) { acc[e][2*jj] = bv.x; acc[e][2*jj+1] = bv.y; }
        }
    }

    unsigned mask = __ballot_sync(FULL, h0v > 0.f) | __ballot_sync(FULL, h1v > 0.f)
                  | __ballot_sync(FULL, h2v > 0.f) | __ballot_sync(FULL, h3v > 0.f);
    while (mask) {
        int k = __ffs(mask) - 1;
        mask &= mask - 1;
        ull k0 = pack2(__shfl_sync(FULL, h0v, k));
        ull k1 = pack2(__shfl_sync(FULL, h1v, k));
        ull k2 = pack2(__shfl_sync(FULL, h2v, k));
        ull k3 = pack2(__shfl_sync(FULL, h3v, k));
        const ulonglong2* wrow = (const ulonglong2*)(ew2 + (size_t)k * HH);
#pragma unroll
        for (int jj = 0; jj < 8; jj++) {
            ulonglong2 wv = wrow[lane + 32 * jj];
            fma2(acc[0][2*jj], k0, wv.x); fma2(acc[0][2*jj+1], k0, wv.y);
            fma2(acc[1][2*jj], k1, wv.x); fma2(acc[1][2*jj+1], k1, wv.y);
            fma2(acc[2][2*jj], k2, wv.x); fma2(acc[2][2*jj+1], k2, wv.y);
            fma2(acc[3][2*jj], k3, wv.x); fma2(acc[3][2*jj+1], k3, wv.y);
        }
    }

    // store fp16
#pragma unroll
    for (int e = 0; e < 4; e++) {
        uint2* dst = (uint2*)(g_We + (size_t)(e4 + e) * HH);
#pragma unroll
        for (int jj = 0; jj < 8; jj++) {
            float2 f01 = unpack2(acc[e][2*jj]);
            float2 f23 = unpack2(acc[e][2*jj+1]);
            __half2 ha = __floats2half2_rn(f01.x, f01.y);
            __half2 hb = __floats2half2_rn(f23.x, f23.y);
            uint2 st;
            st.x = *reinterpret_cast<unsigned*>(&ha);
            st.y = *reinterpret_cast<unsigned*>(&hb);
            dst[lane + 32 * jj] = st;
        }
    }
}

// ---------------------------------------------------------------
// zero agg
// ---------------------------------------------------------------
__global__ __launch_bounds__(256) void k_zero()
{
    size_t i = (size_t)blockIdx.x * blockDim.x + threadIdx.x;
    if (i < (size_t)BB * NN * H) g_agg[i] = 0.f;
}

// ---------------------------------------------------------------
// message + scatter:  agg[b,dst] += node[b,src] @ We[e]   (warp per edge)
// fp16 We: lane (q = lane&15, hi = lane>>4) reads half2 covering
// outputs (2q, 2q+1) of row h = hb + hi. Cross-half reduce at end.
// ---------------------------------------------------------------
__global__ __launch_bounds__(256) void k_msg(
    const int* __restrict__ esrc, const int* __restrict__ edst)
{
    int e    = (blockIdx.x * blockDim.x + threadIdx.x) >> 5;
    int lane = threadIdx.x & 31;
    if (e >= NE) return;

    int s = esrc[e];
    int d = edst[e];
    int hi = lane >> 4;
    int q  = lane & 15;

    float n0 = g_node[(size_t)s * H + lane];
    float n1 = g_node[(size_t)(NN + s) * H + lane];

    const __half2* w = (const __half2*)(g_We + (size_t)e * HH);
    float2 a0 = {0.f, 0.f}, a1 = {0.f, 0.f};
#pragma unroll
    for (int hb = 0; hb < H; hb += 2) {
        __half2 v = __ldcs(w + hb * 16 + lane);   // streaming, 128B/warp
        float2 wf = __half22float2(v);
        int hrow = hb + hi;
        float s0 = __shfl_sync(FULL, n0, hrow);
        float s1 = __shfl_sync(FULL, n1, hrow);
        a0.x = fmaf(s0, wf.x, a0.x); a0.y = fmaf(s0, wf.y, a0.y);
        a1.x = fmaf(s1, wf.x, a1.x); a1.y = fmaf(s1, wf.y, a1.y);
    }
    // combine hi=0 / hi=1 halves (same output columns)
    a0.x += __shfl_xor_sync(FULL, a0.x, 16);
    a0.y += __shfl_xor_sync(FULL, a0.y, 16);
    a1.x += __shfl_xor_sync(FULL, a1.x, 16);
    a1.y += __shfl_xor_sync(FULL, a1.y, 16);

    if (hi == 0) {
        float* p0 = g_agg + (size_t)d * H + 2 * q;
        float* p1 = g_agg + (size_t)(NN + d) * H + 2 * q;
        atomicAdd(p0,     a0.x);
        atomicAdd(p0 + 1, a0.y);
        atomicAdd(p1,     a1.x);
        atomicAdd(p1 + 1, a1.y);
    }
}

// ---------------------------------------------------------------
// node = relu(agg + conv_b); GRU update. Thread per (b,node).
// ---------------------------------------------------------------
__global__ __launch_bounds__(256) void k_gru(
    const float* __restrict__ conv_b,
    const float* __restrict__ wih, const float* __restrict__ whh,
    const float* __restrict__ bih, const float* __restrict__ bhh,
    float* __restrict__ out, int write_out)
{
    int n = blockIdx.x * blockDim.x + threadIdx.x;
    if (n >= BB * NN) return;
    size_t base = (size_t)n * H;

    float nd[H], hd[H];
    {
        const float4* av = (const float4*)(g_agg + base);
        const float4* hv = (const float4*)(g_hidden + base);
        const float4* cv = (const float4*)conv_b;
#pragma unroll
        for (int qq = 0; qq < 8; qq++) {
            float4 a = av[qq], c = cv[qq], h4 = hv[qq];
            nd[4*qq+0] = fmaxf(a.x + c.x, 0.f);
            nd[4*qq+1] = fmaxf(a.y + c.y, 0.f);
            nd[4*qq+2] = fmaxf(a.z + c.z, 0.f);
            nd[4*qq+3] = fmaxf(a.w + c.w, 0.f);
            hd[4*qq+0] = h4.x; hd[4*qq+1] = h4.y; hd[4*qq+2] = h4.z; hd[4*qq+3] = h4.w;
        }
    }

    const float4* wi = (const float4*)wih;   // rows of 8 float4
    const float4* wh = (const float4*)whh;

#pragma unroll 1
    for (int o = 0; o < H; o++) {
        float xr = 0.f, xz = 0.f, xn = 0.f, hr = 0.f, hz = 0.f, hn = 0.f;
#pragma unroll
        for (int qq = 0; qq < 8; qq++) {
            float4 w;
#define DOT(accv, srcarr, row) { w = (row)[qq]; \
            accv = fmaf(srcarr[4*qq+0], w.x, accv); accv = fmaf(srcarr[4*qq+1], w.y, accv); \
            accv = fmaf(srcarr[4*qq+2], w.z, accv); accv = fmaf(srcarr[4*qq+3], w.w, accv); }
            DOT(xr, nd, wi + (size_t)(o)      * 8)
            DOT(xz, nd, wi + (size_t)(o + 32) * 8)
            DOT(xn, nd, wi + (size_t)(o + 64) * 8)
            DOT(hr, hd, wh + (size_t)(o)      * 8)
            DOT(hz, hd, wh + (size_t)(o + 32) * 8)
            DOT(hn, hd, wh + (size_t)(o + 64) * 8)
#undef DOT
        }
        float rg = fsigmoid(xr + hr + bih[o]      + bhh[o]);
        float zg = fsigmoid(xz + hz + bih[o + 32] + bhh[o + 32]);
        float ng = ftanh(xn + bih[o + 64] + rg * (hn + bhh[o + 64]));
        float hprev = hd[o];
        float newh = (1.f - zg) * ng + zg * hprev;
        g_hidden[base + o] = newh;
        g_node[base + o]   = newh;
        if (write_out) out[base + o] = newh;
    }
}

// ---------------------------------------------------------------
extern "C" void kernel_launch(void* const* d_in, const int* in_sizes, int n_in,
                              void* d_out, int out_size)
{
    const float* x      = (const float*)d_in[0];
    const float* rel    = (const float*)d_in[1];
    const float* pw1    = (const float*)d_in[2];
    const float* pb1    = (const float*)d_in[3];
    const float* pw2    = (const float*)d_in[4];
    const float* pb2    = (const float*)d_in[5];
    const float* ew1    = (const float*)d_in[6];
    const float* eb1    = (const float*)d_in[7];
    const float* ew2    = (const float*)d_in[8];
    const float* eb2    = (const float*)d_in[9];
    const float* conv_b = (const float*)d_in[10];
    const float* wih    = (const float*)d_in[11];
    const float* whh    = (const float*)d_in[12];
    const float* bih    = (const float*)d_in[13];
    const float* bhh    = (const float*)d_in[14];
    const int*   esrc   = (const int*)d_in[15];
    const int*   edst   = (const int*)d_in[16];
    float* out = (float*)d_out;

    k_h0<<<13824, 256>>>(x, pw1, pb1, pw2, pb2);
    // 55296 warps (4 edges each) -> 13824 blocks of 128 (4 warps)
    k_We<<<13824, 128>>>(rel, ew1, eb1, ew2, eb2);

    for (int s = 0; s < 3; s++) {
        k_zero<<<13824, 256>>>();
        k_msg<<<27648, 256>>>(esrc, edst);
        k_gru<<<432, 256>>>(conv_b, wih, whh, bih, bhh, out, (s == 2) ? 1 : 0);
    }
}